// round 16
// baseline (speedup 1.0000x reference)
#include <cuda_runtime.h>
#include <cstdint>
#include <math.h>

// Problem constants
constexpr int NN    = 4096;          // number of vertices / matrix dim
constexpr int TPB   = 1024;          // threads per MST block (R14's 512 regressed)
constexpr int SLICE = NN / TPB;      // 4 vertices per thread
constexpr int NWARP = TPB / 32;      // 32 warps

// Scratch (no allocations allowed).
__device__ int g_parent[2][NN];
// Per-row top-2 smallest entries (diagonal excluded) as u64 keys (bits<<32|idx):
// g_top[m][row][0] = smallest, [1] = second smallest. 128KB, L2-hot.
__device__ unsigned long long g_top[2][NN][2];

__device__ __forceinline__ unsigned long long u64min(unsigned long long a, unsigned long long b) {
    return b < a ? b : a;
}
__device__ __forceinline__ unsigned long long u64max(unsigned long long a, unsigned long long b) {
    return b < a ? a : b;
}

// ---------------------------------------------------------------------------
// Preprocessing: per-row top-2 (value,index) keys, diagonal excluded.
// One warp per row, bandwidth-bound (~30us for 128MB). Feeds the speculation
// predictor only — never touches MST correctness.
// ---------------------------------------------------------------------------
__global__ __launch_bounds__(256)
void top2_kernel(const float* __restrict__ d1, const float* __restrict__ d2) {
    const int wglob = (blockIdx.x * blockDim.x + threadIdx.x) >> 5;
    const int lane  = threadIdx.x & 31;
    const int m     = wglob >> 12;           // 0 or 1
    const int row   = wglob & (NN - 1);
    if (m > 1) return;
    const float* __restrict__ D = m ? d2 : d1;

    const float4* r4 = reinterpret_cast<const float4*>(D + (size_t)row * NN);
    unsigned long long k1 = ~0ull, k2 = ~0ull;     // k1 <= k2
    for (int i = lane; i < NN / 4; i += 32) {
        float4 v = r4[i];
        const int base = i * 4;
        float  e[4] = {v.x, v.y, v.z, v.w};
#pragma unroll
        for (int k = 0; k < 4; ++k) {
            const int idx = base + k;
            if (idx != row) {
                unsigned long long kk =
                    ((unsigned long long)__float_as_uint(e[k]) << 32) | (unsigned)idx;
                if (kk < k1) { k2 = k1; k1 = kk; }
                else         { k2 = u64min(k2, kk); }
            }
        }
    }
    // warp merge of sorted pairs: new1 = min(a1,b1); new2 = min(max(a1,b1), min(a2,b2))
#pragma unroll
    for (int o = 16; o; o >>= 1) {
        unsigned long long b1 = __shfl_xor_sync(0xFFFFFFFFu, k1, o);
        unsigned long long b2 = __shfl_xor_sync(0xFFFFFFFFu, k2, o);
        unsigned long long n1 = u64min(k1, b1);
        unsigned long long n2 = u64min(u64max(k1, b1), u64min(k2, b2));
        k1 = n1; k2 = n2;
    }
    if (lane == 0) {
        g_top[m][row][0] = k1;
        g_top[m][row][1] = k2;
    }
}

// ---------------------------------------------------------------------------
// Exact Prim's MST, one persistent CTA per matrix (gridDim.x == 2).
// Core loop = R8 (best measured, rel_err 0.0): u64 keys, REDUX warp phase,
// one barrier, redundant cross-warp phase, sign-bit in-tree encoding,
// strict float < relaxation, cp.async staging into double-buffered smem
// with HIT-CONDITIONAL wait.
//
// R15 upgrade — exact next-winner prediction:
//   Let v = smallest NON-TREE entry of row j (first index on ties), gmin2 =
//   the runner-up. After relaxing row j, every non-tree w has
//   md_new[w] = min(md_old[w], D[j][w]) >= min(gmin2, v), so the next winner
//   is PROVABLY cand (v < gmin2) or j2 (v >= gmin2), ties included (u64 keys
//   carry first-index). cand comes from the precomputed per-row top-2 +
//   an exact smem in-tree bitmap; if both top-2 entries are in-tree we fall
//   back to j2 (only miss case: both in-tree AND a 3rd+ entry wins).
//   Mispredictions only cause a normal LDG — zero correctness coupling.
// Micro: row load issued before the in-tree mark; partials packed as one u64.
// Lessons kept: 128 lines/iter staging (R7 flood), no unconditional wait
// (R12), no persistent reg state (R6), no full-matrix L2 warm (R9).
// ---------------------------------------------------------------------------
__global__ __launch_bounds__(TPB, 1)
void mst_kernel(const float* __restrict__ d1, const float* __restrict__ d2) {
    const float* __restrict__ D = blockIdx.x ? d2 : d1;
    const unsigned long long (* __restrict__ topm)[2] = g_top[blockIdx.x];
    const int t    = threadIdx.x;
    const int wid  = t >> 5;
    const int lane = t & 31;
    constexpr unsigned FULL = 0xFFFFFFFFu;

    // per-warp winner keys (u64: bits<<32|idx), double-buffered
    __shared__ unsigned long long pq[2][NWARP];
    // speculative next-row buffers (double-buffered, 16KB each)
    __shared__ __align__(16) float specbuf[2][NN];
    // exact in-tree bitmap (single writer t0; readers exclude current j manually)
    __shared__ unsigned bm[NN / 32];

    float md[SLICE];
    int   par[SLICE];

    // ---- init ----
    for (int i = t; i < NN / 32; i += TPB) bm[i] = 0;
    {
        float4 a = reinterpret_cast<const float4*>(D)[t];
        md[0] = a.x; md[1] = a.y; md[2] = a.z; md[3] = a.w;
    }
#pragma unroll
    for (int k = 0; k < SLICE; ++k) par[k] = 0;
    if (t == 0) {
        md[0] = __uint_as_float(0xFF800000u);   // vertex 0: -inf => in tree
        bm[0] = 1u;                              // bitmap: vertex 0 in tree
    }

    // thread-local argmin key over owned slice (u64: first-index tie-break)
    unsigned long long key = ~0ull;
#pragma unroll
    for (int k = 0; k < SLICE; ++k) {
        unsigned long long kk =
            ((unsigned long long)__float_as_uint(md[k]) << 32) | (unsigned)(t * SLICE + k);
        key = u64min(key, kk);
    }

    int spec_idx = -1;   // row currently (being) staged in specbuf[(sel-1)&1]

    for (int sel = 0; sel < NN - 1; ++sel) {
        const int s = sel & 1;
        const unsigned bits = (unsigned)(key >> 32);

        // ---- warp phase: REDUX min + first-matching-lane stores its u64 key ----
        const unsigned wmin = __reduce_min_sync(FULL, bits);
        const unsigned ball = __ballot_sync(FULL, bits == wmin);
        const int      wsrc = __ffs((int)ball) - 1;   // first lane == lowest vertex on ties
        if (lane == wsrc) pq[s][wid] = key;
        __syncthreads();

        // ---- cross-warp phase: 32 packed partials, one per lane ----
        const unsigned long long kq = pq[s][lane];
        const unsigned b2 = (unsigned)(kq >> 32);
        const unsigned i2 = (unsigned)kq;
        const unsigned gmin  = __reduce_min_sync(FULL, b2);
        const unsigned ball2 = __ballot_sync(FULL, b2 == gmin);
        const int src = __ffs((int)ball2) - 1;            // lowest warp id with min
        const int j   = (int)__shfl_sync(FULL, i2, src);  // broadcast winner index

        if (sel == NN - 2) {   // last pop: parents already frozen, done
            break;
        }

        // ---- row-j data FIRST (critical path): hit => staged smem, miss => LDG ----
        float4 a;
        if (j == spec_idx) {
            asm volatile("cp.async.wait_all;" ::: "memory");   // own 16B slice staged
            a = reinterpret_cast<const float4*>(&specbuf[s ^ 1][0])[t];
        } else {
            a = reinterpret_cast<const float4*>(D + (size_t)j * NN)[t];
        }

        // ---- mark j in-tree: sign bit (md) + bitmap (single writer) ----
        if ((j >> 2) == t) {
#pragma unroll
            for (int k = 0; k < SLICE; ++k)
                if (k == (j & (SLICE - 1)))
                    md[k] = __uint_as_float(__float_as_uint(md[k]) | 0x80000000u);
        }
        if (t == 0) bm[j >> 5] |= (1u << (j & 31));

        // ---- runner-up j2 + EXACT next-winner prediction; stage spec row ----
        {
            const unsigned bx    = (lane == src) ? 0xFFFFFFFFu : b2;
            const unsigned gmin2 = __reduce_min_sync(FULL, bx);
            const unsigned ball3 = __ballot_sync(FULL, bx == gmin2);
            const int src2 = __ffs((int)ball3) - 1;
            const int j2   = (int)__shfl_sync(FULL, i2, src2);

            int spec = j2;
            if (lane == 0) {
                const unsigned long long t1 = __ldg(&topm[j][0]);
                const unsigned long long t2 = __ldg(&topm[j][1]);
                const int      c1 = (int)(unsigned)t1;
                const unsigned v1 = (unsigned)(t1 >> 32);
                const int      c2 = (int)(unsigned)t2;
                const unsigned v2 = (unsigned)(t2 >> 32);
                // in-tree test: bitmap (complete through sel-1) + explicit j
                const bool ok1 = (c1 != j) && !((bm[c1 >> 5] >> (c1 & 31)) & 1u);
                const bool ok2 = (c2 != j) && !((bm[c2 >> 5] >> (c2 & 31)) & 1u);
                if (ok1)      { if (v1 < gmin2) spec = c1; }
                else if (ok2) { if (v2 < gmin2) spec = c2; }
                // both in-tree: fall back to j2 (only possible miss case)
            }
            spec = __shfl_sync(FULL, spec, 0);   // per-warp broadcast (uniform result)
            spec_idx = spec;

            const float* gsrc = D + (size_t)spec * NN + t * 4;
            const unsigned dsts =
                (unsigned)__cvta_generic_to_shared(&specbuf[s][0]) + (unsigned)(t * 16);
            asm volatile("cp.async.cg.shared.global [%0], [%1], 16;\n"
                         "cp.async.commit_group;\n" :: "r"(dsts), "l"(gsrc) : "memory");
        }

        // ---- relax with row j, fused with local argmin recompute ----
        float rv[SLICE] = {a.x, a.y, a.z, a.w};
        key = ~0ull;
#pragma unroll
        for (int k = 0; k < SLICE; ++k) {
            if (rv[k] < md[k]) { md[k] = rv[k]; par[k] = j; }   // strict <, matches reference
            unsigned long long kk =
                ((unsigned long long)__float_as_uint(md[k]) << 32) | (unsigned)(t * SLICE + k);
            key = u64min(key, kk);
        }
    }

    // drain any outstanding speculative copies before smem goes away
    asm volatile("cp.async.wait_all;" ::: "memory");

    // parents are frozen at pop time; write once at the end
#pragma unroll
    for (int k = 0; k < SLICE; ++k)
        g_parent[blockIdx.x][t * SLICE + k] = par[k];
}

// ---------------------------------------------------------------------------
// Gather signatures, fp64 sums, sqrt, matched-pair count.
// ---------------------------------------------------------------------------
__global__ __launch_bounds__(1024)
void finalize_kernel(const float* __restrict__ d1, const float* __restrict__ d2,
                     float* __restrict__ out, int out_size) {
    constexpr int FT = 1024;
    __shared__ double s12[FT];
    __shared__ double s21[FT];
    __shared__ int    sm[FT];
    const int t = threadIdx.x;

    double a12 = 0.0, a21 = 0.0;
    int m = 0;
#pragma unroll
    for (int i = 0; i < 4; ++i) {
        int c = 1 + t + i * FT;
        if (c < NN) {
            int p1 = g_parent[0][c];
            int p2 = g_parent[1][c];
            float x1 = d1[(size_t)p1 * NN + c];   // sig1
            float y1 = d2[(size_t)p1 * NN + c];   // sig1_2
            float x2 = d2[(size_t)p2 * NN + c];   // sig2
            float y2 = d1[(size_t)p2 * NN + c];   // sig2_1
            double e1 = (double)x1 - (double)y1;
            double e2 = (double)x2 - (double)y2;
            a12 += e1 * e1;
            a21 += e2 * e2;
            m += (p1 == p2);
        }
    }
    s12[t] = a12; s21[t] = a21; sm[t] = m;
    __syncthreads();
#pragma unroll
    for (int o = FT / 2; o; o >>= 1) {
        if (t < o) {
            s12[t] += s12[t + o];
            s21[t] += s21[t + o];
            sm[t]  += sm[t + o];
        }
        __syncthreads();
    }
    if (t == 0) {
        double D12 = sqrt(s12[0]);
        double D21 = sqrt(s21[0]);
        if (out_size > 0) out[0] = (float)(D12 + D21);   // distance
        if (out_size > 1) out[1] = (float)D12;           // distance1_2
        if (out_size > 2) out[2] = (float)D21;           // distance2_1
        if (out_size > 3) out[3] = (float)sm[0];         // matched_pairs
    }
}

extern "C" void kernel_launch(void* const* d_in, const int* in_sizes, int n_in,
                              void* d_out, int out_size) {
    const float* d1 = (const float*)d_in[0];   // distances1 [4096,4096] f32
    const float* d2 = (const float*)d_in[1];   // distances2 [4096,4096] f32
    float* out = (float*)d_out;

    // 1) Per-row top-2 table for the exact next-winner predictor (~30us).
    top2_kernel<<<1024, 256>>>(d1, d2);
    // 2) Two persistent CTAs, one exact Prim's MST each (runs concurrently).
    mst_kernel<<<2, TPB>>>(d1, d2);
    // 3) Tiny epilogue: gathers + fp64 reductions + matched-pair count.
    finalize_kernel<<<1, 1024>>>(d1, d2, out, out_size);
}